// round 11
// baseline (speedup 1.0000x reference)
#include <cuda_runtime.h>
#include <cuda_bf16.h>
#include <cstdint>
#include <math.h>

// Problem dims (fixed)
#define BATCH 64
#define SEQ   512
#define IDIM  256
#define HD    1024
#define MTOT  (BATCH*SEQ)      // 32768
#define RBLK  128              // CTAs in persistent recurrent kernel
#define WSTR  1028             // padded weight column stride (floats)
#define OUT_OFF ((size_t)BATCH*SEQ*HD)
#define DEPTH 8                // h prefetch pipeline depth

typedef unsigned long long ull;

// ---------------- scratch (device globals: no allocs allowed) ----------------
__device__ float g_xp[(size_t)MTOT * HD];                 // 128 MB
__device__ float g_gate[(size_t)3 * SEQ * BATCH * HD];    // 384 MB, [g][t][b][h]
// h and rh in TRANSPOSED-TILED layout: [k/4][row][4]
//   float idx = (k>>2)*256 + r*4 + (k&3)   -> double2 idx = (k>>2)*64 + r
__device__ float g_h[BATCH * HD];
__device__ float g_rh[BATCH * HD];
__device__ unsigned g_bar_count;
__device__ unsigned g_bar_gen;

// ---------------- packed f32x2 helpers ----------------
__device__ __forceinline__ void ffma2(ull& d, ull a, ull b) {
    asm("fma.rn.f32x2 %0, %1, %2, %0;" : "+l"(d) : "l"(a), "l"(b));
}
__device__ __forceinline__ ull d2l(double x) { return __double_as_longlong(x); }
__device__ __forceinline__ ull dupf(float x) {
    ull d; unsigned u = __float_as_uint(x);
    asm("mov.b64 %0, {%1, %1};" : "=l"(d) : "r"(u));
    return d;
}
__device__ __forceinline__ float hadd2(ull a, ull b) {
    unsigned alo, ahi, blo, bhi;
    asm("mov.b64 {%0, %1}, %2;" : "=r"(alo), "=r"(ahi) : "l"(a));
    asm("mov.b64 {%0, %1}, %2;" : "=r"(blo), "=r"(bhi) : "l"(b));
    return (__uint_as_float(alo) + __uint_as_float(ahi)) +
           (__uint_as_float(blo) + __uint_as_float(bhi));
}

// ---------------- grid-wide barrier ----------------
__device__ __forceinline__ void grid_sync() {
    __threadfence();          // release: h/rh stores -> L2 visible
    __syncthreads();
    if (threadIdx.x == 0) {
        unsigned gen = ((volatile unsigned*)&g_bar_gen)[0];
        unsigned arrived = atomicAdd(&g_bar_count, 1u);
        if (arrived == gridDim.x - 1) {
            g_bar_count = 0;
            __threadfence();
            atomicAdd(&g_bar_gen, 1u);
        } else {
            while (((volatile unsigned*)&g_bar_gen)[0] == gen) { __nanosleep(20); }
        }
    }
    __syncthreads();
    __threadfence_block();
}

__device__ __forceinline__ float sigmoidf_(float x) {
    return 1.0f / (1.0f + __expf(-x));
}

// ---------------- init: zero transposed h (also shifts ncu -s 5 onto gru_rec)
__global__ void init_h() {
    const int i = blockIdx.x * blockDim.x + threadIdx.x;
    ((float4*)g_h)[i] = make_float4(0.f, 0.f, 0.f, 0.f);   // 16384 float4
}

// ---------------- SGEMM: C = A[MxK] * B[KxN] + bias, optional row remap ------
__global__ __launch_bounds__(256, 2)
void sgemm128(const float* __restrict__ A, const float* __restrict__ B,
              const float* __restrict__ bias, float* __restrict__ C,
              int M, int N, int K, int remap)
{
    __shared__ float As[2][16][128];
    __shared__ float Bs[2][16][128];

    const int tid = threadIdx.x;
    const int bm = blockIdx.y * 128;
    const int bn = blockIdx.x * 128;

    const int tm = (tid >> 4) * 8;
    const int tn = (tid & 15) * 8;

    ull accp[4][8];
#pragma unroll
    for (int i = 0; i < 4; ++i)
#pragma unroll
        for (int j = 0; j < 8; ++j) accp[i][j] = 0ull;

    const int arow = tid >> 2;
    const int acol = (tid & 3) * 4;
    const int brow = tid >> 5;
    const int bcol = (tid & 31) * 4;

    const float* Ag = A + (size_t)(bm + arow) * K + acol;
    const float* Bg = B + (size_t)brow * N + bn + bcol;

    {
        float4 a0 = *(const float4*)(Ag);
        float4 a1 = *(const float4*)(Ag + (size_t)64 * K);
        float4 b0 = *(const float4*)(Bg);
        float4 b1 = *(const float4*)(Bg + (size_t)8 * N);
        As[0][acol + 0][arow] = a0.x; As[0][acol + 1][arow] = a0.y;
        As[0][acol + 2][arow] = a0.z; As[0][acol + 3][arow] = a0.w;
        As[0][acol + 0][arow + 64] = a1.x; As[0][acol + 1][arow + 64] = a1.y;
        As[0][acol + 2][arow + 64] = a1.z; As[0][acol + 3][arow + 64] = a1.w;
        *(float4*)&Bs[0][brow][bcol] = b0;
        *(float4*)&Bs[0][brow + 8][bcol] = b1;
    }
    __syncthreads();

    int buf = 0;
    for (int kt = 0; kt < K; kt += 16) {
        const int nkt = kt + 16;
        const bool more = (nkt < K);
        float4 a0, a1, b0, b1;
        if (more) {
            a0 = *(const float4*)(Ag + nkt);
            a1 = *(const float4*)(Ag + (size_t)64 * K + nkt);
            b0 = *(const float4*)(Bg + (size_t)nkt * N);
            b1 = *(const float4*)(Bg + (size_t)(nkt + 8) * N);
        }
        const float (*as)[128] = As[buf];
        const float (*bs)[128] = Bs[buf];
#pragma unroll
        for (int kk = 0; kk < 16; ++kk) {
            const double2 pA = *(const double2*)&as[kk][tm];
            const double2 pB = *(const double2*)&as[kk][tm + 4];
            const ull pa[4] = { d2l(pA.x), d2l(pA.y), d2l(pB.x), d2l(pB.y) };
            const float4 pb0 = *(const float4*)&bs[kk][tn];
            const float4 pb1 = *(const float4*)&bs[kk][tn + 4];
            const ull pbd[8] = { dupf(pb0.x), dupf(pb0.y), dupf(pb0.z), dupf(pb0.w),
                                 dupf(pb1.x), dupf(pb1.y), dupf(pb1.z), dupf(pb1.w) };
#pragma unroll
            for (int i2 = 0; i2 < 4; ++i2)
#pragma unroll
                for (int j = 0; j < 8; ++j)
                    ffma2(accp[i2][j], pa[i2], pbd[j]);
        }
        if (more) {
            const int nb = buf ^ 1;
            As[nb][acol + 0][arow] = a0.x; As[nb][acol + 1][arow] = a0.y;
            As[nb][acol + 2][arow] = a0.z; As[nb][acol + 3][arow] = a0.w;
            As[nb][acol + 0][arow + 64] = a1.x; As[nb][acol + 1][arow + 64] = a1.y;
            As[nb][acol + 2][arow + 64] = a1.z; As[nb][acol + 3][arow + 64] = a1.w;
            *(float4*)&Bs[nb][brow][bcol] = b0;
            *(float4*)&Bs[nb][brow + 8][bcol] = b1;
        }
        __syncthreads();
        buf ^= 1;
    }

    float bl[8];
#pragma unroll
    for (int j = 0; j < 8; ++j) bl[j] = bias[bn + tn + j];

#pragma unroll
    for (int i2 = 0; i2 < 4; ++i2) {
        float r0v[8], r1v[8];
#pragma unroll
        for (int j = 0; j < 8; ++j) {
            unsigned lo, hi;
            asm("mov.b64 {%0, %1}, %2;" : "=r"(lo), "=r"(hi) : "l"(accp[i2][j]));
            r0v[j] = __uint_as_float(lo) + bl[j];
            r1v[j] = __uint_as_float(hi) + bl[j];
        }
#pragma unroll
        for (int s = 0; s < 2; ++s) {
            const int m = bm + tm + i2 * 2 + s;
            const size_t orow = remap ? ((size_t)(m & (SEQ - 1)) * BATCH + (m >> 9))
                                      : (size_t)m;
            float* crow = C + orow * N + bn + tn;
            const float* rv = s ? r1v : r0v;
            *(float4*)(crow)     = make_float4(rv[0], rv[1], rv[2], rv[3]);
            *(float4*)(crow + 4) = make_float4(rv[4], rv[5], rv[6], rv[7]);
        }
    }
}

// ---------------- persistent recurrent kernel ----------------
// 128 CTAs x 128 threads. Thread owns (1 col, 4 rows {rb,rb+16,rb+32,rb+48}).
// h/rh transposed [k/4][row][4]: a warp's 4 rows at double2 idx u*64+w*4+{0..3}
// form one contiguous 64B segment (1 L1TEX wavefront/LDG, 8-lane broadcast).
// Weights in padded smem (conflict-free, reused over 4 rows). Depth-8 prefetch.
__global__ __launch_bounds__(128, 1)
void gru_rec(const float* __restrict__ Wzh, const float* __restrict__ Wrh,
             const float* __restrict__ Wnh, float* __restrict__ out)
{
    extern __shared__ float smem[];
    float* wz_s = smem;                  // 8 cols x WSTR
    float* wr_s = smem + 8 * WSTR;
    float* wn_s = smem + 16 * WSTR;

    const int tid = threadIdx.x;
    const int c0 = blockIdx.x * 8;

    for (int i = tid; i < 8 * HD; i += 128) {
        const int k = i >> 3, c = i & 7;
        wz_s[c * WSTR + k] = Wzh[(size_t)k * HD + c0 + c];
        wr_s[c * WSTR + k] = Wrh[(size_t)k * HD + c0 + c];
        wn_s[c * WSTR + k] = Wnh[(size_t)k * HD + c0 + c];
    }
    __syncthreads();   // h zeroed by init_h (stream-ordered); gates by sgemms

    const int l   = tid & 31;
    const int w   = tid >> 5;           // warp 0..3
    const int cl  = l & 7;
    const int rgl = l >> 3;             // 0..3
    const int col = c0 + cl;
    const int rb  = w * 4 + rgl;        // rows rb + 16*i, i=0..3

    const double2* wz2 = (const double2*)(wz_s + cl * WSTR);
    const double2* wr2 = (const double2*)(wr_s + cl * WSTR);
    const double2* wn2 = (const double2*)(wn_s + cl * WSTR);

    const float* gz = g_gate;
    const float* gr = g_gate + (size_t)SEQ * BATCH * HD;
    const float* gn = g_gate + (size_t)2 * SEQ * BATCH * HD;

    const double2* ht2  = (const double2*)g_h;    // double2 idx = u*64 + r
    const double2* rht2 = (const double2*)g_rh;

    // scalar slot of (r, col) in transposed layout
    const int cslot = (col >> 2) * 256 + (col & 3);

    double2 hp[DEPTH][4];               // prefetch pipeline

    for (int t = 0; t < SEQ; ++t) {
        // ---- Phase A: z = sig(xz + h@Wz_h), r = sig(xr + h@Wr_h), rh = r*h
        ull accz[4][2], accr[4][2];
#pragma unroll
        for (int i = 0; i < 4; ++i) {
            accz[i][0] = accz[i][1] = 0ull;
            accr[i][0] = accr[i][1] = 0ull;
        }
#pragma unroll
        for (int s = 0; s < DEPTH; ++s)
#pragma unroll
            for (int i = 0; i < 4; ++i)
                hp[s][i] = __ldcg(ht2 + s * 64 + (rb + 16 * i));

#pragma unroll 8
        for (int u = 0; u < 256; ++u) {
            const int s = u & (DEPTH - 1);
            const double2 wz = wz2[u], wr = wr2[u];
            const ull wzx = d2l(wz.x), wzy = d2l(wz.y);
            const ull wrx = d2l(wr.x), wry = d2l(wr.y);
#pragma unroll
            for (int i = 0; i < 4; ++i) {
                const ull hx = d2l(hp[s][i].x), hy = d2l(hp[s][i].y);
                ffma2(accz[i][0], hx, wzx); ffma2(accz[i][1], hy, wzy);
                ffma2(accr[i][0], hx, wrx); ffma2(accr[i][1], hy, wry);
            }
            if (u + DEPTH < 256) {
#pragma unroll
                for (int i = 0; i < 4; ++i)
                    hp[s][i] = __ldcg(ht2 + (u + DEPTH) * 64 + (rb + 16 * i));
            }
        }

        float zf[4], hv[4];
        const int gbase = (t * BATCH + rb) * HD + col;
#pragma unroll
        for (int i = 0; i < 4; ++i) {
            const int r = rb + 16 * i;
            const int gi = gbase + 16 * i * HD;
            hv[i] = __ldcg(g_h + cslot + r * 4);
            zf[i] = sigmoidf_(hadd2(accz[i][0], accz[i][1]) + __ldg(gz + gi));
            const float rv = sigmoidf_(hadd2(accr[i][0], accr[i][1]) + __ldg(gr + gi));
            g_rh[cslot + r * 4] = rv * hv[i];
        }

        grid_sync();

        // ---- Phase B: n = tanh(xn + rh@Wn_h), h' = (1-z)n + z h
        ull accn[4][2];
#pragma unroll
        for (int i = 0; i < 4; ++i) { accn[i][0] = accn[i][1] = 0ull; }
#pragma unroll
        for (int s = 0; s < DEPTH; ++s)
#pragma unroll
            for (int i = 0; i < 4; ++i)
                hp[s][i] = __ldcg(rht2 + s * 64 + (rb + 16 * i));

#pragma unroll 8
        for (int u = 0; u < 256; ++u) {
            const int s = u & (DEPTH - 1);
            const double2 wn = wn2[u];
            const ull wnx = d2l(wn.x), wny = d2l(wn.y);
#pragma unroll
            for (int i = 0; i < 4; ++i) {
                ffma2(accn[i][0], d2l(hp[s][i].x), wnx);
                ffma2(accn[i][1], d2l(hp[s][i].y), wny);
            }
            if (u + DEPTH < 256) {
#pragma unroll
                for (int i = 0; i < 4; ++i)
                    hp[s][i] = __ldcg(rht2 + (u + DEPTH) * 64 + (rb + 16 * i));
            }
        }

#pragma unroll
        for (int i = 0; i < 4; ++i) {
            const int r = rb + 16 * i;
            const int gi = gbase + 16 * i * HD;
            const float n = tanhf(hadd2(accn[i][0], accn[i][1]) + __ldg(gn + gi));
            const float hn = (1.0f - zf[i]) * n + zf[i] * hv[i];
            g_h[cslot + r * 4] = hn;
            out[((size_t)r * SEQ + t) * HD + col] = hn;
            if (t == SEQ - 1)
                out[OUT_OFF + (size_t)r * HD + col] = hn;
        }

        grid_sync();
    }
}

// ---------------- launch ----------------
extern "C" void kernel_launch(void* const* d_in, const int* in_sizes, int n_in,
                              void* d_out, int out_size)
{
    const float* x  = (const float*)d_in[0];
    const float* Wi = (const float*)d_in[1];
    const float* bi = (const float*)d_in[2];
    const float* Wz = (const float*)d_in[3];
    const float* bz = (const float*)d_in[4];
    const float* Wr = (const float*)d_in[5];
    const float* br = (const float*)d_in[6];
    const float* Wn = (const float*)d_in[7];
    const float* bn = (const float*)d_in[8];
    float* out = (float*)d_out;

    float* xp;   cudaGetSymbolAddress((void**)&xp,   g_xp);
    float* gate; cudaGetSymbolAddress((void**)&gate, g_gate);

    const dim3 gg(HD / 128, MTOT / 128);   // (8, 256)

    init_h<<<64, 256>>>();                 // zero transposed h (launch #1 of 6)
    sgemm128<<<gg, 256>>>(x, Wi, bi, xp, MTOT, HD, IDIM, 0);
    sgemm128<<<gg, 256>>>(xp, Wz, bz, gate,                                MTOT, HD, HD, 1);
    sgemm128<<<gg, 256>>>(xp, Wr, br, gate + (size_t)SEQ * BATCH * HD,     MTOT, HD, HD, 1);
    sgemm128<<<gg, 256>>>(xp, Wn, bn, gate + (size_t)2 * SEQ * BATCH * HD, MTOT, HD, HD, 1);

    cudaFuncSetAttribute(gru_rec, cudaFuncAttributeMaxDynamicSharedMemorySize, 24 * WSTR * 4);
    gru_rec<<<RBLK, 128, 24 * WSTR * 4>>>(Wz + (size_t)HD * HD,
                                          Wr + (size_t)HD * HD,
                                          Wn + (size_t)HD * HD, out);
}

// round 13
// speedup vs baseline: 1.1262x; 1.1262x over previous
#include <cuda_runtime.h>
#include <cuda_bf16.h>
#include <cstdint>
#include <math.h>

// Problem dims (fixed)
#define BATCH 64
#define SEQ   512
#define IDIM  256
#define HD    1024
#define MTOT  (BATCH*SEQ)      // 32768
#define WSTR  1028             // padded weight column stride (floats)
#define OUT_OFF ((size_t)BATCH*SEQ*HD)
// recurrence partitioning: 2 independent batch groups x 64 CTAs x 16 cols
#define NGRP  2
#define GCTAS 64
#define GROWS 32               // batch rows per group

typedef unsigned long long ull;

// ---------------- scratch (device globals: no allocs allowed) ----------------
__device__ float g_xp[(size_t)MTOT * HD];                 // 128 MB
__device__ float g_gate[(size_t)3 * SEQ * BATCH * HD];    // 384 MB, [g][t][b][h]
__device__ float g_h[BATCH * HD];                         // row-major [b][h]
__device__ float g_rh[BATCH * HD];
__device__ unsigned g_bar_cnt[NGRP * 32];                 // 128B-separated cells
__device__ unsigned g_bar_gen[NGRP * 32];

// ---------------- packed f32x2 helpers ----------------
__device__ __forceinline__ void ffma2(ull& d, ull a, ull b) {
    asm("fma.rn.f32x2 %0, %1, %2, %0;" : "+l"(d) : "l"(a), "l"(b));
}
__device__ __forceinline__ ull d2l(double x) { return __double_as_longlong(x); }
__device__ __forceinline__ ull dupf(float x) {
    ull d; unsigned u = __float_as_uint(x);
    asm("mov.b64 %0, {%1, %1};" : "=l"(d) : "r"(u));
    return d;
}
__device__ __forceinline__ float hadd2(ull a, ull b) {
    unsigned alo, ahi, blo, bhi;
    asm("mov.b64 {%0, %1}, %2;" : "=r"(alo), "=r"(ahi) : "l"(a));
    asm("mov.b64 {%0, %1}, %2;" : "=r"(blo), "=r"(bhi) : "l"(b));
    return (__uint_as_float(alo) + __uint_as_float(ahi)) +
           (__uint_as_float(blo) + __uint_as_float(bhi));
}

// ---------------- fence-free release/acquire group barrier ----------------
// Arrival: atom.release (orders all prior CTA stores via preceding syncthreads).
// Wait: spin ld.acquire (no nanosleep quantum, no MEMBAR, no CCTL.IVALL).
__device__ __forceinline__ void group_sync(unsigned* cnt, unsigned* gen) {
    __syncthreads();
    if (threadIdx.x == 0) {
        unsigned g0;
        asm volatile("ld.acquire.gpu.global.b32 %0, [%1];" : "=r"(g0) : "l"(gen));
        unsigned arrived;
        asm volatile("atom.release.gpu.global.add.u32 %0, [%1], %2;"
                     : "=r"(arrived) : "l"(cnt), "r"(1u));
        if (arrived == GCTAS - 1) {
            asm volatile("st.relaxed.gpu.global.b32 [%0], %1;" :: "l"(cnt), "r"(0u));
            asm volatile("red.release.gpu.global.add.u32 [%0], %1;" :: "l"(gen), "r"(1u));
        } else {
            unsigned cur;
            do {
                asm volatile("ld.acquire.gpu.global.b32 %0, [%1];" : "=r"(cur) : "l"(gen));
            } while (cur == g0);
        }
    }
    __syncthreads();
}

__device__ __forceinline__ float sigmoidf_(float x) {
    return 1.0f / (1.0f + __expf(-x));
}

// ---------------- init: zero h ----------------
__global__ void init_h() {
    const int i = blockIdx.x * blockDim.x + threadIdx.x;
    ((float4*)g_h)[i] = make_float4(0.f, 0.f, 0.f, 0.f);   // 16384 float4
}

// ---------------- SGEMM: C = A[MxK] * B[KxN] + bias, optional row remap ------
__global__ __launch_bounds__(256, 2)
void sgemm128(const float* __restrict__ A, const float* __restrict__ B,
              const float* __restrict__ bias, float* __restrict__ C,
              int M, int N, int K, int remap)
{
    __shared__ float As[2][16][128];
    __shared__ float Bs[2][16][128];

    const int tid = threadIdx.x;
    const int bm = blockIdx.y * 128;
    const int bn = blockIdx.x * 128;

    const int tm = (tid >> 4) * 8;
    const int tn = (tid & 15) * 8;

    ull accp[4][8];
#pragma unroll
    for (int i = 0; i < 4; ++i)
#pragma unroll
        for (int j = 0; j < 8; ++j) accp[i][j] = 0ull;

    const int arow = tid >> 2;
    const int acol = (tid & 3) * 4;
    const int brow = tid >> 5;
    const int bcol = (tid & 31) * 4;

    const float* Ag = A + (size_t)(bm + arow) * K + acol;
    const float* Bg = B + (size_t)brow * N + bn + bcol;

    {
        float4 a0 = *(const float4*)(Ag);
        float4 a1 = *(const float4*)(Ag + (size_t)64 * K);
        float4 b0 = *(const float4*)(Bg);
        float4 b1 = *(const float4*)(Bg + (size_t)8 * N);
        As[0][acol + 0][arow] = a0.x; As[0][acol + 1][arow] = a0.y;
        As[0][acol + 2][arow] = a0.z; As[0][acol + 3][arow] = a0.w;
        As[0][acol + 0][arow + 64] = a1.x; As[0][acol + 1][arow + 64] = a1.y;
        As[0][acol + 2][arow + 64] = a1.z; As[0][acol + 3][arow + 64] = a1.w;
        *(float4*)&Bs[0][brow][bcol] = b0;
        *(float4*)&Bs[0][brow + 8][bcol] = b1;
    }
    __syncthreads();

    int buf = 0;
    for (int kt = 0; kt < K; kt += 16) {
        const int nkt = kt + 16;
        const bool more = (nkt < K);
        float4 a0, a1, b0, b1;
        if (more) {
            a0 = *(const float4*)(Ag + nkt);
            a1 = *(const float4*)(Ag + (size_t)64 * K + nkt);
            b0 = *(const float4*)(Bg + (size_t)nkt * N);
            b1 = *(const float4*)(Bg + (size_t)(nkt + 8) * N);
        }
        const float (*as)[128] = As[buf];
        const float (*bs)[128] = Bs[buf];
#pragma unroll
        for (int kk = 0; kk < 16; ++kk) {
            const double2 pA = *(const double2*)&as[kk][tm];
            const double2 pB = *(const double2*)&as[kk][tm + 4];
            const ull pa[4] = { d2l(pA.x), d2l(pA.y), d2l(pB.x), d2l(pB.y) };
            const float4 pb0 = *(const float4*)&bs[kk][tn];
            const float4 pb1 = *(const float4*)&bs[kk][tn + 4];
            const ull pbd[8] = { dupf(pb0.x), dupf(pb0.y), dupf(pb0.z), dupf(pb0.w),
                                 dupf(pb1.x), dupf(pb1.y), dupf(pb1.z), dupf(pb1.w) };
#pragma unroll
            for (int i2 = 0; i2 < 4; ++i2)
#pragma unroll
                for (int j = 0; j < 8; ++j)
                    ffma2(accp[i2][j], pa[i2], pbd[j]);
        }
        if (more) {
            const int nb = buf ^ 1;
            As[nb][acol + 0][arow] = a0.x; As[nb][acol + 1][arow] = a0.y;
            As[nb][acol + 2][arow] = a0.z; As[nb][acol + 3][arow] = a0.w;
            As[nb][acol + 0][arow + 64] = a1.x; As[nb][acol + 1][arow + 64] = a1.y;
            As[nb][acol + 2][arow + 64] = a1.z; As[nb][acol + 3][arow + 64] = a1.w;
            *(float4*)&Bs[nb][brow][bcol] = b0;
            *(float4*)&Bs[nb][brow + 8][bcol] = b1;
        }
        __syncthreads();
        buf ^= 1;
    }

    float bl[8];
#pragma unroll
    for (int j = 0; j < 8; ++j) bl[j] = bias[bn + tn + j];

#pragma unroll
    for (int i2 = 0; i2 < 4; ++i2) {
        float r0v[8], r1v[8];
#pragma unroll
        for (int j = 0; j < 8; ++j) {
            unsigned lo, hi;
            asm("mov.b64 {%0, %1}, %2;" : "=r"(lo), "=r"(hi) : "l"(accp[i2][j]));
            r0v[j] = __uint_as_float(lo) + bl[j];
            r1v[j] = __uint_as_float(hi) + bl[j];
        }
#pragma unroll
        for (int s = 0; s < 2; ++s) {
            const int m = bm + tm + i2 * 2 + s;
            const size_t orow = remap ? ((size_t)(m & (SEQ - 1)) * BATCH + (m >> 9))
                                      : (size_t)m;
            float* crow = C + orow * N + bn + tn;
            const float* rv = s ? r1v : r0v;
            *(float4*)(crow)     = make_float4(rv[0], rv[1], rv[2], rv[3]);
            *(float4*)(crow + 4) = make_float4(rv[4], rv[5], rv[6], rv[7]);
        }
    }
}

// ---------------- persistent recurrent kernel (one t-range) ----------------
// 128 CTAs = 2 groups x 64. Group handles 32 batch rows independently.
// CTA owns 16 H-cols (weights 192.75KB smem, padded conflict-free). Thread:
// (1 col, 2 rows). Fence-free 64-CTA release/acquire barrier per group.
__global__ __launch_bounds__(256, 1)
void gru_rec(const float* __restrict__ Wzh, const float* __restrict__ Wrh,
             const float* __restrict__ Wnh, float* __restrict__ out,
             int t0, int t1)
{
    extern __shared__ float smem[];
    float* wz_s = smem;                  // 16 cols x WSTR
    float* wr_s = smem + 16 * WSTR;
    float* wn_s = smem + 32 * WSTR;

    const int tid = threadIdx.x;
    const int grp = blockIdx.x >> 6;            // 0..1
    const int c0  = (blockIdx.x & 63) * 16;

    for (int i = tid; i < 16 * HD; i += 256) {
        const int k = i >> 4, c = i & 15;
        wz_s[c * WSTR + k] = Wzh[(size_t)k * HD + c0 + c];
        wr_s[c * WSTR + k] = Wrh[(size_t)k * HD + c0 + c];
        wn_s[c * WSTR + k] = Wnh[(size_t)k * HD + c0 + c];
    }

    unsigned* cnt = &g_bar_cnt[grp * 32];
    unsigned* gen = &g_bar_gen[grp * 32];

    const int cl  = tid & 15;
    const int col = c0 + cl;
    const int r0  = grp * GROWS + (tid >> 4) * 2;   // rows r0, r0+1
    const double2* wz2 = (const double2*)(wz_s + cl * WSTR);
    const double2* wr2 = (const double2*)(wr_s + cl * WSTR);
    const double2* wn2 = (const double2*)(wn_s + cl * WSTR);

    const float* gz = g_gate;
    const float* gr = g_gate + (size_t)SEQ * BATCH * HD;
    const float* gn = g_gate + (size_t)2 * SEQ * BATCH * HD;

    const double2* h0p  = (const double2*)(g_h + r0 * HD);
    const double2* h1p  = (const double2*)(g_h + (r0 + 1) * HD);
    const double2* rh0p = (const double2*)(g_rh + r0 * HD);
    const double2* rh1p = (const double2*)(g_rh + (r0 + 1) * HD);

    group_sync(cnt, gen);   // weights staged; h init visible (stream order)

    for (int t = t0; t < t1; ++t) {
        // ---- Phase A: z = sig(xz + h@Wz_h), r = sig(xr + h@Wr_h), rh = r*h
        const int gidx0 = (t * BATCH + r0) * HD + col;
        const int gidx1 = gidx0 + HD;
        const float xz0 = __ldg(gz + gidx0);
        const float xz1 = __ldg(gz + gidx1);
        const float xr0 = __ldg(gr + gidx0);
        const float xr1 = __ldg(gr + gidx1);
        const float h0v = __ldcg(g_h + r0 * HD + col);
        const float h1v = __ldcg(g_h + (r0 + 1) * HD + col);

        ull az0a = 0, az0b = 0, az1a = 0, az1b = 0;
        ull ar0a = 0, ar0b = 0, ar1a = 0, ar1b = 0;
        double2 A0[4], A1[4], B0[4], B1[4];

#define LOADH(b0, b1, base) { _Pragma("unroll") \
        for (int j = 0; j < 4; ++j) { b0[j] = __ldcg(h0p + (base) + j); b1[j] = __ldcg(h1p + (base) + j); } }
#define COMPA(b0, b1, base) { _Pragma("unroll") \
        for (int j = 0; j < 4; ++j) { \
            const double2 wz = wz2[(base) + j], wr = wr2[(base) + j]; \
            const ull h0l = d2l(b0[j].x), h0h = d2l(b0[j].y); \
            const ull h1l = d2l(b1[j].x), h1h = d2l(b1[j].y); \
            ffma2(az0a, h0l, d2l(wz.x)); ffma2(az0b, h0h, d2l(wz.y)); \
            ffma2(az1a, h1l, d2l(wz.x)); ffma2(az1b, h1h, d2l(wz.y)); \
            ffma2(ar0a, h0l, d2l(wr.x)); ffma2(ar0b, h0h, d2l(wr.y)); \
            ffma2(ar1a, h1l, d2l(wr.x)); ffma2(ar1b, h1h, d2l(wr.y)); } }

        LOADH(A0, A1, 0);
        for (int blk = 0; blk < 64; blk += 2) {
            LOADH(B0, B1, (blk + 1) * 4);
            COMPA(A0, A1, blk * 4);
            if (blk + 2 < 64) { LOADH(A0, A1, (blk + 2) * 4); }
            COMPA(B0, B1, (blk + 1) * 4);
        }

        const float z0 = sigmoidf_(hadd2(az0a, az0b) + xz0);
        const float z1 = sigmoidf_(hadd2(az1a, az1b) + xz1);
        const float rv0 = sigmoidf_(hadd2(ar0a, ar0b) + xr0);
        const float rv1 = sigmoidf_(hadd2(ar1a, ar1b) + xr1);
        g_rh[r0 * HD + col]       = rv0 * h0v;
        g_rh[(r0 + 1) * HD + col] = rv1 * h1v;

        group_sync(cnt, gen);

        // ---- Phase B: n = tanh(xn + rh@Wn_h), h' = (1-z)n + z h
        const float xn0 = __ldg(gn + gidx0);
        const float xn1 = __ldg(gn + gidx1);

        ull an0a = 0, an0b = 0, an1a = 0, an1b = 0;

#define LOADR(b0, b1, base) { _Pragma("unroll") \
        for (int j = 0; j < 4; ++j) { b0[j] = __ldcg(rh0p + (base) + j); b1[j] = __ldcg(rh1p + (base) + j); } }
#define COMPB(b0, b1, base) { _Pragma("unroll") \
        for (int j = 0; j < 4; ++j) { \
            const double2 wn = wn2[(base) + j]; \
            ffma2(an0a, d2l(b0[j].x), d2l(wn.x)); ffma2(an0b, d2l(b0[j].y), d2l(wn.y)); \
            ffma2(an1a, d2l(b1[j].x), d2l(wn.x)); ffma2(an1b, d2l(b1[j].y), d2l(wn.y)); } }

        LOADR(A0, A1, 0);
        for (int blk = 0; blk < 64; blk += 2) {
            LOADR(B0, B1, (blk + 1) * 4);
            COMPB(A0, A1, blk * 4);
            if (blk + 2 < 64) { LOADR(A0, A1, (blk + 2) * 4); }
            COMPB(B0, B1, (blk + 1) * 4);
        }

        const float n0 = tanhf(hadd2(an0a, an0b) + xn0);
        const float n1 = tanhf(hadd2(an1a, an1b) + xn1);
        const float hn0 = (1.0f - z0) * n0 + z0 * h0v;
        const float hn1 = (1.0f - z1) * n1 + z1 * h1v;
        g_h[r0 * HD + col]       = hn0;
        g_h[(r0 + 1) * HD + col] = hn1;
        __stcs(out + ((size_t)r0 * SEQ + t) * HD + col, hn0);
        __stcs(out + ((size_t)(r0 + 1) * SEQ + t) * HD + col, hn1);
        if (t == SEQ - 1) {
            __stcs(out + OUT_OFF + (size_t)r0 * HD + col, hn0);
            __stcs(out + OUT_OFF + (size_t)(r0 + 1) * HD + col, hn1);
        }

        group_sync(cnt, gen);
    }
}

// ---------------- launch ----------------
extern "C" void kernel_launch(void* const* d_in, const int* in_sizes, int n_in,
                              void* d_out, int out_size)
{
    const float* x  = (const float*)d_in[0];
    const float* Wi = (const float*)d_in[1];
    const float* bi = (const float*)d_in[2];
    const float* Wz = (const float*)d_in[3];
    const float* bz = (const float*)d_in[4];
    const float* Wr = (const float*)d_in[5];
    const float* br = (const float*)d_in[6];
    const float* Wn = (const float*)d_in[7];
    const float* bn = (const float*)d_in[8];
    float* out = (float*)d_out;

    float* xp;   cudaGetSymbolAddress((void**)&xp,   g_xp);
    float* gate; cudaGetSymbolAddress((void**)&gate, g_gate);

    const dim3 gg(HD / 128, MTOT / 128);   // (8, 256)

    init_h<<<64, 256>>>();
    sgemm128<<<gg, 256>>>(x, Wi, bi, xp, MTOT, HD, IDIM, 0);
    sgemm128<<<gg, 256>>>(xp, Wz, bz, gate,                                MTOT, HD, HD, 1);
    sgemm128<<<gg, 256>>>(xp, Wr, br, gate + (size_t)SEQ * BATCH * HD,     MTOT, HD, HD, 1);
    sgemm128<<<gg, 256>>>(xp, Wn, bn, gate + (size_t)2 * SEQ * BATCH * HD, MTOT, HD, HD, 1);

    const int smem_rec = 48 * WSTR * 4;    // 197,376 B
    cudaFuncSetAttribute(gru_rec, cudaFuncAttributeMaxDynamicSharedMemorySize, smem_rec);
    // two half-sequence launches: free inter-launch sync; ncu -s 5 lands on one
    gru_rec<<<NGRP * GCTAS, 256, smem_rec>>>(Wz + (size_t)HD * HD,
                                             Wr + (size_t)HD * HD,
                                             Wn + (size_t)HD * HD, out, 0, SEQ / 2);
    gru_rec<<<NGRP * GCTAS, 256, smem_rec>>>(Wz + (size_t)HD * HD,
                                             Wr + (size_t)HD * HD,
                                             Wn + (size_t)HD * HD, out, SEQ / 2, SEQ);
}

// round 15
// speedup vs baseline: 1.1618x; 1.0316x over previous
#include <cuda_runtime.h>
#include <cuda_bf16.h>
#include <cstdint>
#include <math.h>

// Problem dims (fixed)
#define BATCH 64
#define SEQ   512
#define IDIM  256
#define HD    1024
#define MTOT  (BATCH*SEQ)      // 32768
#define WSTR  1028             // padded weight column stride (floats)
#define OUT_OFF ((size_t)BATCH*SEQ*HD)
#define NGRP  2
#define GCTAS 64
#define GROWS 32

// tf32 GEMM tiling
#define KT 32                  // k-tile
#define AS_STRIDE 36
#define BS_STRIDE 132
#define AS_FLOATS (128 * AS_STRIDE)
#define BS_FLOATS (32 * BS_STRIDE)
#define SMEM_GEMM ((2 * AS_FLOATS + 2 * BS_FLOATS) * 4)   // 70656 B

typedef unsigned long long ull;

// ---------------- scratch (device globals: no allocs allowed) ----------------
__device__ float g_xp[(size_t)MTOT * HD];                 // 128 MB
__device__ float g_gate[(size_t)3 * SEQ * BATCH * HD];    // 384 MB, [g][t][b][h]
__device__ float g_h[BATCH * HD];
__device__ float g_rh[BATCH * HD];
__device__ unsigned g_bar_cnt[NGRP * 32];
__device__ unsigned g_bar_gen[NGRP * 32];

// ---------------- packed f32x2 helpers (recurrence) ----------------
__device__ __forceinline__ void ffma2(ull& d, ull a, ull b) {
    asm("fma.rn.f32x2 %0, %1, %2, %0;" : "+l"(d) : "l"(a), "l"(b));
}
__device__ __forceinline__ ull d2l(double x) { return __double_as_longlong(x); }
__device__ __forceinline__ float hadd2(ull a, ull b) {
    unsigned alo, ahi, blo, bhi;
    asm("mov.b64 {%0, %1}, %2;" : "=r"(alo), "=r"(ahi) : "l"(a));
    asm("mov.b64 {%0, %1}, %2;" : "=r"(blo), "=r"(bhi) : "l"(b));
    return (__uint_as_float(alo) + __uint_as_float(ahi)) +
           (__uint_as_float(blo) + __uint_as_float(bhi));
}

// ---------------- fence-free release/acquire group barrier ----------------
__device__ __forceinline__ void group_sync(unsigned* cnt, unsigned* gen) {
    __syncthreads();
    if (threadIdx.x == 0) {
        unsigned g0;
        asm volatile("ld.acquire.gpu.global.b32 %0, [%1];" : "=r"(g0) : "l"(gen));
        unsigned arrived;
        asm volatile("atom.release.gpu.global.add.u32 %0, [%1], %2;"
                     : "=r"(arrived) : "l"(cnt), "r"(1u));
        if (arrived == GCTAS - 1) {
            asm volatile("st.relaxed.gpu.global.b32 [%0], %1;" :: "l"(cnt), "r"(0u));
            asm volatile("red.release.gpu.global.add.u32 [%0], %1;" :: "l"(gen), "r"(1u));
        } else {
            unsigned cur;
            do {
                asm volatile("ld.acquire.gpu.global.b32 %0, [%1];" : "=r"(cur) : "l"(gen));
            } while (cur == g0);
        }
    }
    __syncthreads();
}

__device__ __forceinline__ float sigmoidf_(float x) {
    return 1.0f / (1.0f + __expf(-x));
}

// ---------------- init: zero h ----------------
__global__ void init_h() {
    const int i = blockIdx.x * blockDim.x + threadIdx.x;
    ((float4*)g_h)[i] = make_float4(0.f, 0.f, 0.f, 0.f);
}

// ---------------- 3xTF32 tensor-core GEMM ----------------
// C = A[MxK] @ B[KxN] + bias; fp32-emulation via hi/lo tf32 split:
//   acc += hi_a*hi_b + lo_a*hi_b + hi_a*lo_b   (~22-bit operand precision)
__device__ __forceinline__ unsigned tf32h(float x) {
    unsigned u; asm("cvt.rna.tf32.f32 %0, %1;" : "=r"(u) : "f"(x)); return u;
}
__device__ __forceinline__ void tf32split(float x, unsigned& hi, unsigned& lo) {
    hi = tf32h(x);
    lo = tf32h(x - __uint_as_float(hi));
}

__device__ __forceinline__ void mma_tf32(float* c, const unsigned* a, const unsigned* b) {
    asm("mma.sync.aligned.m16n8k8.row.col.f32.tf32.tf32.f32 "
        "{%0,%1,%2,%3}, {%4,%5,%6,%7}, {%8,%9}, {%0,%1,%2,%3};"
        : "+f"(c[0]), "+f"(c[1]), "+f"(c[2]), "+f"(c[3])
        : "r"(a[0]), "r"(a[1]), "r"(a[2]), "r"(a[3]), "r"(b[0]), "r"(b[1]));
}

#define CP16(dst_u32, src_ptr) \
    asm volatile("cp.async.cg.shared.global [%0], [%1], 16;" \
                 :: "r"(dst_u32), "l"(src_ptr) : "memory")

__global__ __launch_bounds__(256, 2)
void sgemm_tf32(const float* __restrict__ A, const float* __restrict__ B,
                const float* __restrict__ bias, float* __restrict__ C,
                int M, int N, int K, int remap)
{
    extern __shared__ float smem[];
    float* as_base = smem;                       // 2 x [128][36]
    float* bs_base = smem + 2 * AS_FLOATS;       // 2 x [32][132]
    unsigned smem_u32;
    {
        unsigned long long tmp;
        asm("cvta.to.shared.u64 %0, %1;" : "=l"(tmp) : "l"(smem));
        smem_u32 = (unsigned)tmp;
    }

    const int tid = threadIdx.x;
    const int lane = tid & 31;
    const int wid = tid >> 5;
    const int wm = (wid & 3) * 32;
    const int wn = (wid >> 2) * 64;
    const int gid = lane >> 2;
    const int tig = lane & 3;

    const int bm = blockIdx.y * 128;
    const int bn = blockIdx.x * 128;

    float acc[2][8][4];
#pragma unroll
    for (int mf = 0; mf < 2; ++mf)
#pragma unroll
        for (int nf = 0; nf < 8; ++nf)
#pragma unroll
            for (int v = 0; v < 4; ++v) acc[mf][nf][v] = 0.0f;

    const int a_row = tid >> 1;
    const int a_col = (tid & 1) * 16;
    const int b_row = tid >> 3;
    const int b_col = (tid & 7) * 16;

    const float* Ag = A + (size_t)(bm + a_row) * K + a_col;
    const float* Bg = B + (size_t)b_row * N + bn + b_col;
    const unsigned as_u = smem_u32 + (a_row * AS_STRIDE + a_col) * 4;
    const unsigned bs_u = smem_u32 + (2 * AS_FLOATS + b_row * BS_STRIDE + b_col) * 4;

#define CPTILE(kt, buf) { \
        const float* ag = Ag + (kt) * KT; \
        const float* bg = Bg + (size_t)(kt) * KT * N; \
        const unsigned ad = as_u + (buf) * AS_FLOATS * 4; \
        const unsigned bd = bs_u + (buf) * BS_FLOATS * 4; \
        CP16(ad,      ag);      CP16(ad + 16, ag + 4); \
        CP16(ad + 32, ag + 8);  CP16(ad + 48, ag + 12); \
        CP16(bd,      bg);      CP16(bd + 16, bg + 4); \
        CP16(bd + 32, bg + 8);  CP16(bd + 48, bg + 12); \
        asm volatile("cp.async.commit_group;" ::: "memory"); }

    const int kTiles = K / KT;
    CPTILE(0, 0);

    for (int kt = 0; kt < kTiles; ++kt) {
        const int buf = kt & 1;
        if (kt + 1 < kTiles) {
            CPTILE(kt + 1, buf ^ 1);
            asm volatile("cp.async.wait_group 1;" ::: "memory");
        } else {
            asm volatile("cp.async.wait_group 0;" ::: "memory");
        }
        __syncthreads();

        const float* as = as_base + buf * AS_FLOATS;
        const float* bs = bs_base + buf * BS_FLOATS;
#pragma unroll
        for (int kk = 0; kk < KT; kk += 8) {
            // A fragments: hi/lo split (persist over nf loop)
            unsigned afh[2][4], afl[2][4];
#pragma unroll
            for (int mf = 0; mf < 2; ++mf) {
                const int r = wm + mf * 16 + gid;
                tf32split(as[r * AS_STRIDE + kk + tig],           afh[mf][0], afl[mf][0]);
                tf32split(as[(r + 8) * AS_STRIDE + kk + tig],     afh[mf][1], afl[mf][1]);
                tf32split(as[r * AS_STRIDE + kk + tig + 4],       afh[mf][2], afl[mf][2]);
                tf32split(as[(r + 8) * AS_STRIDE + kk + tig + 4], afh[mf][3], afl[mf][3]);
            }
            // B fragments converted per-nf (short live range -> fits 128 regs)
#pragma unroll
            for (int nf = 0; nf < 8; ++nf) {
                const int c = wn + nf * 8 + gid;
                unsigned bh[2], bl_[2];
                tf32split(bs[(kk + tig) * BS_STRIDE + c],     bh[0], bl_[0]);
                tf32split(bs[(kk + tig + 4) * BS_STRIDE + c], bh[1], bl_[1]);
#pragma unroll
                for (int mf = 0; mf < 2; ++mf) {
                    mma_tf32(acc[mf][nf], afh[mf], bh);
                    mma_tf32(acc[mf][nf], afl[mf], bh);
                    mma_tf32(acc[mf][nf], afh[mf], bl_);
                }
            }
        }
        __syncthreads();
    }

    // epilogue: bias + (optional) time-major remap
#pragma unroll
    for (int mf = 0; mf < 2; ++mf) {
#pragma unroll
        for (int h = 0; h < 2; ++h) {
            const int m = bm + wm + mf * 16 + gid + h * 8;
            const size_t orow = remap ? ((size_t)(m & (SEQ - 1)) * BATCH + (m >> 9))
                                      : (size_t)m;
            float* crow = C + orow * N + bn;
#pragma unroll
            for (int nf = 0; nf < 8; ++nf) {
                const int c = wn + nf * 8 + 2 * tig;
                float2 v;
                v.x = acc[mf][nf][h * 2 + 0] + bias[bn + c];
                v.y = acc[mf][nf][h * 2 + 1] + bias[bn + c + 1];
                *(float2*)(crow + c) = v;
            }
        }
    }
}

// ---------------- persistent recurrent kernel (round-13 best, unchanged) ----
__global__ __launch_bounds__(256, 1)
void gru_rec(const float* __restrict__ Wzh, const float* __restrict__ Wrh,
             const float* __restrict__ Wnh, float* __restrict__ out,
             int t0, int t1)
{
    extern __shared__ float smem[];
    float* wz_s = smem;                  // 16 cols x WSTR
    float* wr_s = smem + 16 * WSTR;
    float* wn_s = smem + 32 * WSTR;

    const int tid = threadIdx.x;
    const int grp = blockIdx.x >> 6;
    const int c0  = (blockIdx.x & 63) * 16;

    for (int i = tid; i < 16 * HD; i += 256) {
        const int k = i >> 4, c = i & 15;
        wz_s[c * WSTR + k] = Wzh[(size_t)k * HD + c0 + c];
        wr_s[c * WSTR + k] = Wrh[(size_t)k * HD + c0 + c];
        wn_s[c * WSTR + k] = Wnh[(size_t)k * HD + c0 + c];
    }

    unsigned* cnt = &g_bar_cnt[grp * 32];
    unsigned* gen = &g_bar_gen[grp * 32];

    const int cl  = tid & 15;
    const int col = c0 + cl;
    const int r0  = grp * GROWS + (tid >> 4) * 2;
    const double2* wz2 = (const double2*)(wz_s + cl * WSTR);
    const double2* wr2 = (const double2*)(wr_s + cl * WSTR);
    const double2* wn2 = (const double2*)(wn_s + cl * WSTR);

    const float* gz = g_gate;
    const float* gr = g_gate + (size_t)SEQ * BATCH * HD;
    const float* gn = g_gate + (size_t)2 * SEQ * BATCH * HD;

    const double2* h0p  = (const double2*)(g_h + r0 * HD);
    const double2* h1p  = (const double2*)(g_h + (r0 + 1) * HD);
    const double2* rh0p = (const double2*)(g_rh + r0 * HD);
    const double2* rh1p = (const double2*)(g_rh + (r0 + 1) * HD);

    group_sync(cnt, gen);

    for (int t = t0; t < t1; ++t) {
        const int gidx0 = (t * BATCH + r0) * HD + col;
        const int gidx1 = gidx0 + HD;
        const float xz0 = __ldg(gz + gidx0);
        const float xz1 = __ldg(gz + gidx1);
        const float xr0 = __ldg(gr + gidx0);
        const float xr1 = __ldg(gr + gidx1);
        const float h0v = __ldcg(g_h + r0 * HD + col);
        const float h1v = __ldcg(g_h + (r0 + 1) * HD + col);

        ull az0a = 0, az0b = 0, az1a = 0, az1b = 0;
        ull ar0a = 0, ar0b = 0, ar1a = 0, ar1b = 0;
        double2 A0[4], A1[4], B0[4], B1[4];

#define LOADH(b0, b1, base) { _Pragma("unroll") \
        for (int j = 0; j < 4; ++j) { b0[j] = __ldcg(h0p + (base) + j); b1[j] = __ldcg(h1p + (base) + j); } }
#define COMPA(b0, b1, base) { _Pragma("unroll") \
        for (int j = 0; j < 4; ++j) { \
            const double2 wz = wz2[(base) + j], wr = wr2[(base) + j]; \
            const ull h0l = d2l(b0[j].x), h0h = d2l(b0[j].y); \
            const ull h1l = d2l(b1[j].x), h1h = d2l(b1[j].y); \
            ffma2(az0a, h0l, d2l(wz.x)); ffma2(az0b, h0h, d2l(wz.y)); \
            ffma2(az1a, h1l, d2l(wz.x)); ffma2(az1b, h1h, d2l(wz.y)); \
            ffma2(ar0a, h0l, d2l(wr.x)); ffma2(ar0b, h0h, d2l(wr.y)); \
            ffma2(ar1a, h1l, d2l(wr.x)); ffma2(ar1b, h1h, d2l(wr.y)); } }

        LOADH(A0, A1, 0);
        for (int blk = 0; blk < 64; blk += 2) {
            LOADH(B0, B1, (blk + 1) * 4);
            COMPA(A0, A1, blk * 4);
            if (blk + 2 < 64) { LOADH(A0, A1, (blk + 2) * 4); }
            COMPA(B0, B1, (blk + 1) * 4);
        }

        const float z0 = sigmoidf_(hadd2(az0a, az0b) + xz0);
        const float z1 = sigmoidf_(hadd2(az1a, az1b) + xz1);
        const float rv0 = sigmoidf_(hadd2(ar0a, ar0b) + xr0);
        const float rv1 = sigmoidf_(hadd2(ar1a, ar1b) + xr1);
        g_rh[r0 * HD + col]       = rv0 * h0v;
        g_rh[(r0 + 1) * HD + col] = rv1 * h1v;

        group_sync(cnt, gen);

        const float xn0 = __ldg(gn + gidx0);
        const float xn1 = __ldg(gn + gidx1);

        ull an0a = 0, an0b = 0, an1a = 0, an1b = 0;

#define LOADR(b0, b1, base) { _Pragma("unroll") \
        for (int j = 0; j < 4; ++j) { b0[j] = __ldcg(rh0p + (base) + j); b1[j] = __ldcg(rh1p + (base) + j); } }
#define COMPB(b0, b1, base) { _Pragma("unroll") \
        for (int j = 0; j < 4; ++j) { \
            const double2 wn = wn2[(base) + j]; \
            ffma2(an0a, d2l(b0[j].x), d2l(wn.x)); ffma2(an0b, d2l(b0[j].y), d2l(wn.y)); \
            ffma2(an1a, d2l(b1[j].x), d2l(wn.x)); ffma2(an1b, d2l(b1[j].y), d2l(wn.y)); } }

        LOADR(A0, A1, 0);
        for (int blk = 0; blk < 64; blk += 2) {
            LOADR(B0, B1, (blk + 1) * 4);
            COMPB(A0, A1, blk * 4);
            if (blk + 2 < 64) { LOADR(A0, A1, (blk + 2) * 4); }
            COMPB(B0, B1, (blk + 1) * 4);
        }

        const float n0 = tanhf(hadd2(an0a, an0b) + xn0);
        const float n1 = tanhf(hadd2(an1a, an1b) + xn1);
        const float hn0 = (1.0f - z0) * n0 + z0 * h0v;
        const float hn1 = (1.0f - z1) * n1 + z1 * h1v;
        g_h[r0 * HD + col]       = hn0;
        g_h[(r0 + 1) * HD + col] = hn1;
        __stcs(out + ((size_t)r0 * SEQ + t) * HD + col, hn0);
        __stcs(out + ((size_t)(r0 + 1) * SEQ + t) * HD + col, hn1);
        if (t == SEQ - 1) {
            __stcs(out + OUT_OFF + (size_t)r0 * HD + col, hn0);
            __stcs(out + OUT_OFF + (size_t)(r0 + 1) * HD + col, hn1);
        }

        group_sync(cnt, gen);
    }
}

// ---------------- launch ----------------
extern "C" void kernel_launch(void* const* d_in, const int* in_sizes, int n_in,
                              void* d_out, int out_size)
{
    const float* x  = (const float*)d_in[0];
    const float* Wi = (const float*)d_in[1];
    const float* bi = (const float*)d_in[2];
    const float* Wz = (const float*)d_in[3];
    const float* bz = (const float*)d_in[4];
    const float* Wr = (const float*)d_in[5];
    const float* br = (const float*)d_in[6];
    const float* Wn = (const float*)d_in[7];
    const float* bn = (const float*)d_in[8];
    float* out = (float*)d_out;

    float* xp;   cudaGetSymbolAddress((void**)&xp,   g_xp);
    float* gate; cudaGetSymbolAddress((void**)&gate, g_gate);

    const dim3 gg(HD / 128, MTOT / 128);   // (8, 256)

    init_h<<<64, 256>>>();

    cudaFuncSetAttribute(sgemm_tf32, cudaFuncAttributeMaxDynamicSharedMemorySize, SMEM_GEMM);
    sgemm_tf32<<<gg, 256, SMEM_GEMM>>>(x, Wi, bi, xp, MTOT, HD, IDIM, 0);
    sgemm_tf32<<<gg, 256, SMEM_GEMM>>>(xp, Wz, bz, gate,                                MTOT, HD, HD, 1);
    sgemm_tf32<<<gg, 256, SMEM_GEMM>>>(xp, Wr, br, gate + (size_t)SEQ * BATCH * HD,     MTOT, HD, HD, 1);
    sgemm_tf32<<<gg, 256, SMEM_GEMM>>>(xp, Wn, bn, gate + (size_t)2 * SEQ * BATCH * HD, MTOT, HD, HD, 1);

    const int smem_rec = 48 * WSTR * 4;
    cudaFuncSetAttribute(gru_rec, cudaFuncAttributeMaxDynamicSharedMemorySize, smem_rec);
    gru_rec<<<NGRP * GCTAS, 256, smem_rec>>>(Wz + (size_t)HD * HD,
                                             Wr + (size_t)HD * HD,
                                             Wn + (size_t)HD * HD, out, 0, SEQ / 2);
    gru_rec<<<NGRP * GCTAS, 256, smem_rec>>>(Wz + (size_t)HD * HD,
                                             Wr + (size_t)HD * HD,
                                             Wn + (size_t)HD * HD, out, SEQ / 2, SEQ);
}

// round 16
// speedup vs baseline: 1.3892x; 1.1958x over previous
#include <cuda_runtime.h>
#include <cuda_bf16.h>
#include <cstdint>
#include <math.h>

// Problem dims (fixed)
#define BATCH 64
#define SEQ   512
#define IDIM  256
#define HD    1024
#define MTOT  (BATCH*SEQ)      // 32768
#define OUT_OFF ((size_t)BATCH*SEQ*HD)
#define RCTAS 128              // recurrence CTAs (1 group)

// tf32 GEMM tiling (parallel phase)
#define KT 32
#define AS_STRIDE 36
#define BS_STRIDE 132
#define AS_FLOATS (128 * AS_STRIDE)
#define BS_FLOATS (32 * BS_STRIDE)
#define SMEM_GEMM ((2 * AS_FLOATS + 2 * BS_FLOATS) * 4)   // 70656 B

// recurrence weight pack: per col-block(8 cols): [gate(3)][hilo(2)][s(128)][tig(4)][colj(8)][pair(2)]
#define WPK_BLOCK 49152        // words per col-block
#define SMEM_REC  (WPK_BLOCK * 4 + 4096)   // weights + 1024-float reduction buf

typedef unsigned long long ull;

// ---------------- scratch (device globals: no allocs allowed) ----------------
__device__ float g_xp[(size_t)MTOT * HD];                 // 128 MB
__device__ float g_gate[(size_t)3 * SEQ * BATCH * HD];    // 384 MB, [g][t][b][h]
__device__ float g_h[BATCH * HD];                         // fp32 row-major [b][h]
__device__ unsigned g_hA_hi[BATCH * HD];                  // packed A-frag layout
__device__ unsigned g_hA_lo[BATCH * HD];
__device__ unsigned g_rhA_hi[BATCH * HD];
__device__ unsigned g_rhA_lo[BATCH * HD];
__device__ unsigned g_wpk[(size_t)RCTAS * WPK_BLOCK];     // 24 MB packed weights
__device__ unsigned g_bar_cnt[32];
__device__ unsigned g_bar_gen[32];

// ---------------- tf32 helpers ----------------
__device__ __forceinline__ unsigned tf32h(float x) {
    unsigned u; asm("cvt.rna.tf32.f32 %0, %1;" : "=r"(u) : "f"(x)); return u;
}
__device__ __forceinline__ void tf32split(float x, unsigned& hi, unsigned& lo) {
    hi = tf32h(x);
    lo = tf32h(x - __uint_as_float(hi));
}
__device__ __forceinline__ void mma_tf32(float* c, const unsigned* a, const unsigned* b) {
    asm("mma.sync.aligned.m16n8k8.row.col.f32.tf32.tf32.f32 "
        "{%0,%1,%2,%3}, {%4,%5,%6,%7}, {%8,%9}, {%0,%1,%2,%3};"
        : "+f"(c[0]), "+f"(c[1]), "+f"(c[2]), "+f"(c[3])
        : "r"(a[0]), "r"(a[1]), "r"(a[2]), "r"(a[3]), "r"(b[0]), "r"(b[1]));
}
// 3xTF32: hh + lh + hl
__device__ __forceinline__ void mma3(float* c, const unsigned* aH, const unsigned* aL,
                                     uint2 bh, uint2 bl) {
    unsigned bhv[2] = {bh.x, bh.y};
    unsigned blv[2] = {bl.x, bl.y};
    mma_tf32(c, aH, bhv);
    mma_tf32(c, aL, bhv);
    mma_tf32(c, aH, blv);
}

// ---------------- fence-free release/acquire grid barrier (128 CTAs) --------
__device__ __forceinline__ void group_sync(unsigned* cnt, unsigned* gen) {
    __syncthreads();
    if (threadIdx.x == 0) {
        unsigned g0;
        asm volatile("ld.acquire.gpu.global.b32 %0, [%1];" : "=r"(g0) : "l"(gen));
        unsigned arrived;
        asm volatile("atom.acq_rel.gpu.global.add.u32 %0, [%1], %2;"
                     : "=r"(arrived) : "l"(cnt), "r"(1u));
        if (arrived == RCTAS - 1) {
            asm volatile("st.relaxed.gpu.global.b32 [%0], %1;" :: "l"(cnt), "r"(0u));
            asm volatile("red.release.gpu.global.add.u32 [%0], %1;" :: "l"(gen), "r"(1u));
        } else {
            unsigned cur;
            do {
                asm volatile("ld.acquire.gpu.global.b32 %0, [%1];" : "=r"(cur) : "l"(gen));
            } while (cur == g0);
        }
    }
    __syncthreads();
}

__device__ __forceinline__ float sigmoidf_(float x) {
    return 1.0f / (1.0f + __expf(-x));
}

// ---------------- init: zero h (fp32 + packed hi/lo) ----------------
__global__ void init_h() {
    const int i = blockIdx.x * blockDim.x + threadIdx.x;   // 0..49151
    const float4 z = make_float4(0.f, 0.f, 0.f, 0.f);
    if (i < 16384)       ((float4*)g_h)[i] = z;
    else if (i < 32768)  ((float4*)g_hA_hi)[i - 16384] = z;
    else                 ((float4*)g_hA_lo)[i - 32768] = z;
}

// ---------------- prep: pack recurrent weights (hi/lo, B-fragment order) ----
__global__ void prep_w(const float* __restrict__ Wz, const float* __restrict__ Wr,
                       const float* __restrict__ Wn) {
    const size_t i = (size_t)blockIdx.x * 256 + threadIdx.x;   // 3*1024*1024
    const int g = (int)(i >> 20);
    const int rem = (int)(i & 0xFFFFF);
    const int k = rem >> 10, c = rem & 1023;
    const float* W = (g == 0) ? Wz : ((g == 1) ? Wr : Wn);
    const float v = W[(size_t)(HD + k) * HD + c];
    unsigned hi, lo; tf32split(v, hi, lo);
    const int cb = c >> 3, colj = c & 7;
    const int s = k >> 3, j = k & 7, tg = j & 3, p = j >> 2;
    const size_t base = (size_t)cb * WPK_BLOCK;
    const size_t off = ((size_t)s) * 64 + tg * 16 + colj * 2 + p;
    g_wpk[base + ((size_t)(g * 2 + 0) * 128) * 64 + off] = hi;
    g_wpk[base + ((size_t)(g * 2 + 1) * 128) * 64 + off] = lo;
}

// ---------------- 3xTF32 tensor-core GEMM (parallel phase, from r15) --------
#define CP16(dst_u32, src_ptr) \
    asm volatile("cp.async.cg.shared.global [%0], [%1], 16;" \
                 :: "r"(dst_u32), "l"(src_ptr) : "memory")

__global__ __launch_bounds__(256, 2)
void sgemm_tf32(const float* __restrict__ A, const float* __restrict__ B,
                const float* __restrict__ bias, float* __restrict__ C,
                int M, int N, int K, int remap)
{
    extern __shared__ float smem[];
    float* as_base = smem;
    float* bs_base = smem + 2 * AS_FLOATS;
    unsigned smem_u32;
    {
        unsigned long long tmp;
        asm("cvta.to.shared.u64 %0, %1;" : "=l"(tmp) : "l"(smem));
        smem_u32 = (unsigned)tmp;
    }

    const int tid = threadIdx.x;
    const int lane = tid & 31;
    const int wid = tid >> 5;
    const int wm = (wid & 3) * 32;
    const int wn = (wid >> 2) * 64;
    const int gid = lane >> 2;
    const int tig = lane & 3;

    const int bm = blockIdx.y * 128;
    const int bn = blockIdx.x * 128;

    float acc[2][8][4];
#pragma unroll
    for (int mf = 0; mf < 2; ++mf)
#pragma unroll
        for (int nf = 0; nf < 8; ++nf)
#pragma unroll
            for (int v = 0; v < 4; ++v) acc[mf][nf][v] = 0.0f;

    const int a_row = tid >> 1;
    const int a_col = (tid & 1) * 16;
    const int b_row = tid >> 3;
    const int b_col = (tid & 7) * 16;

    const float* Ag = A + (size_t)(bm + a_row) * K + a_col;
    const float* Bg = B + (size_t)b_row * N + bn + b_col;
    const unsigned as_u = smem_u32 + (a_row * AS_STRIDE + a_col) * 4;
    const unsigned bs_u = smem_u32 + (2 * AS_FLOATS + b_row * BS_STRIDE + b_col) * 4;

#define CPTILE(kt, buf) { \
        const float* ag = Ag + (kt) * KT; \
        const float* bg = Bg + (size_t)(kt) * KT * N; \
        const unsigned ad = as_u + (buf) * AS_FLOATS * 4; \
        const unsigned bd = bs_u + (buf) * BS_FLOATS * 4; \
        CP16(ad,      ag);      CP16(ad + 16, ag + 4); \
        CP16(ad + 32, ag + 8);  CP16(ad + 48, ag + 12); \
        CP16(bd,      bg);      CP16(bd + 16, bg + 4); \
        CP16(bd + 32, bg + 8);  CP16(bd + 48, bg + 12); \
        asm volatile("cp.async.commit_group;" ::: "memory"); }

    const int kTiles = K / KT;
    CPTILE(0, 0);

    for (int kt = 0; kt < kTiles; ++kt) {
        const int buf = kt & 1;
        if (kt + 1 < kTiles) {
            CPTILE(kt + 1, buf ^ 1);
            asm volatile("cp.async.wait_group 1;" ::: "memory");
        } else {
            asm volatile("cp.async.wait_group 0;" ::: "memory");
        }
        __syncthreads();

        const float* as = as_base + buf * AS_FLOATS;
        const float* bs = bs_base + buf * BS_FLOATS;
#pragma unroll
        for (int kk = 0; kk < KT; kk += 8) {
            unsigned afh[2][4], afl[2][4];
#pragma unroll
            for (int mf = 0; mf < 2; ++mf) {
                const int r = wm + mf * 16 + gid;
                tf32split(as[r * AS_STRIDE + kk + tig],           afh[mf][0], afl[mf][0]);
                tf32split(as[(r + 8) * AS_STRIDE + kk + tig],     afh[mf][1], afl[mf][1]);
                tf32split(as[r * AS_STRIDE + kk + tig + 4],       afh[mf][2], afl[mf][2]);
                tf32split(as[(r + 8) * AS_STRIDE + kk + tig + 4], afh[mf][3], afl[mf][3]);
            }
#pragma unroll
            for (int nf = 0; nf < 8; ++nf) {
                const int c = wn + nf * 8 + gid;
                unsigned bh[2], bl_[2];
                tf32split(bs[(kk + tig) * BS_STRIDE + c],     bh[0], bl_[0]);
                tf32split(bs[(kk + tig + 4) * BS_STRIDE + c], bh[1], bl_[1]);
#pragma unroll
                for (int mf = 0; mf < 2; ++mf) {
                    mma_tf32(acc[mf][nf], afh[mf], bh);
                    mma_tf32(acc[mf][nf], afl[mf], bh);
                    mma_tf32(acc[mf][nf], afh[mf], bl_);
                }
            }
        }
        __syncthreads();
    }

#pragma unroll
    for (int mf = 0; mf < 2; ++mf) {
#pragma unroll
        for (int h = 0; h < 2; ++h) {
            const int m = bm + wm + mf * 16 + gid + h * 8;
            const size_t orow = remap ? ((size_t)(m & (SEQ - 1)) * BATCH + (m >> 9))
                                      : (size_t)m;
            float* crow = C + orow * N + bn;
#pragma unroll
            for (int nf = 0; nf < 8; ++nf) {
                const int c = wn + nf * 8 + 2 * tig;
                float2 v;
                v.x = acc[mf][nf][h * 2 + 0] + bias[bn + c];
                v.y = acc[mf][nf][h * 2 + 1] + bias[bn + c + 1];
                *(float2*)(crow + c) = v;
            }
        }
    }
}

// ---------------- tensor-core persistent recurrence ----------------
// 128 CTAs x 8 warps. CTA owns 8 H-cols; packed hi/lo weights in smem.
// Warp = (m-tile mt, k-half kh). A-frags (h/rh) from packed global via
// coalesced LDG.64 (.cg). 3xTF32: hh + lh + hl. k-half reduce via smem.
__global__ __launch_bounds__(256, 1)
void gru_rec_tc(float* __restrict__ out, int t0, int t1)
{
    extern __shared__ unsigned smemu[];
    unsigned* w_s = smemu;                       // 49152 words
    float* red = (float*)(smemu + WPK_BLOCK);    // 1024 floats

    const int tid = threadIdx.x;
    const int cb = blockIdx.x;                   // col block: cols cb*8..+7

    // stage packed weights (contiguous 196,608 B)
    {
        const float4* src = (const float4*)(g_wpk + (size_t)cb * WPK_BLOCK);
        float4* dst = (float4*)w_s;
#pragma unroll
        for (int i = 0; i < 48; ++i)
            dst[tid + i * 256] = __ldg(src + tid + i * 256);
    }
    __syncthreads();

    const int lane = tid & 31, w = tid >> 5;
    const int gid = lane >> 2, tig = lane & 3;
    const int mt = w & 3, kh = w >> 2;
    const int rA = mt * 16 + gid, rB = rA + 8;
    const int ccol0 = cb * 8 + 2 * tig, ccol1 = ccol0 + 1;
    const int s0 = kh * 64;

    const uint2* ws2  = (const uint2*)w_s;       // idx = (g*2+e)*4096 + s*32 + tig*8 + gid
    const uint2* hHi  = (const uint2*)g_hA_hi;   // idx = (s*64 + r)*4 + tig
    const uint2* hLo  = (const uint2*)g_hA_lo;
    const uint2* rhHi = (const uint2*)g_rhA_hi;
    const uint2* rhLo = (const uint2*)g_rhA_lo;

    const float* gz = g_gate;
    const float* gr = g_gate + (size_t)SEQ * BATCH * HD;
    const float* gn = g_gate + (size_t)2 * SEQ * BATCH * HD;

    unsigned* cnt = &g_bar_cnt[0];
    unsigned* gen = &g_bar_gen[0];

    float zf[4] = {0, 0, 0, 0}, hv[4] = {0, 0, 0, 0};

    for (int t = t0; t < t1; ++t) {
        // ---- Phase A: z/r pre-activations via mma, then rh = sig(r)*h ----
        float cz[4] = {0, 0, 0, 0}, cr[4] = {0, 0, 0, 0};
#pragma unroll 4
        for (int s = s0; s < s0 + 64; ++s) {
            const int ai0 = (s * 64 + rA) * 4 + tig;
            const int ai1 = (s * 64 + rB) * 4 + tig;
            const uint2 ah0 = __ldcg(hHi + ai0);
            const uint2 ah1 = __ldcg(hHi + ai1);
            const uint2 al0 = __ldcg(hLo + ai0);
            const uint2 al1 = __ldcg(hLo + ai1);
            const unsigned aH[4] = {ah0.x, ah1.x, ah0.y, ah1.y};
            const unsigned aL[4] = {al0.x, al1.x, al0.y, al1.y};
            const int bi = s * 32 + tig * 8 + gid;
            mma3(cz, aH, aL, ws2[bi],            ws2[4096 + bi]);
            mma3(cr, aH, aL, ws2[2 * 4096 + bi], ws2[3 * 4096 + bi]);
        }
        if (kh == 1) {
            float* rb = red + (mt * 32 + lane) * 8;
#pragma unroll
            for (int i = 0; i < 4; ++i) { rb[i] = cz[i]; rb[i + 4] = cr[i]; }
        }
        __syncthreads();
        if (kh == 0) {
            const float* rb = red + (mt * 32 + lane) * 8;
#pragma unroll
            for (int i = 0; i < 4; ++i) { cz[i] += rb[i]; cr[i] += rb[i + 4]; }
#pragma unroll
            for (int v = 0; v < 4; ++v) {
                const int row = (v < 2) ? rA : rB;
                const int col = (v & 1) ? ccol1 : ccol0;
                const size_t gidx = ((size_t)t * BATCH + row) * HD + col;
                zf[v] = sigmoidf_(cz[v] + __ldg(gz + gidx));
                const float rv = sigmoidf_(cr[v] + __ldg(gr + gidx));
                hv[v] = __ldcg(g_h + row * HD + col);
                const float rh = rv * hv[v];
                unsigned hi, lo; tf32split(rh, hi, lo);
                const int j = col & 7;
                const int word = (((col >> 3) * 64 + row) * 4 + (j & 3)) * 2 + (j >> 2);
                g_rhA_hi[word] = hi;
                g_rhA_lo[word] = lo;
            }
        }
        group_sync(cnt, gen);

        // ---- Phase B: n pre-activation via mma, then h' ----
        float cn[4] = {0, 0, 0, 0};
#pragma unroll 4
        for (int s = s0; s < s0 + 64; ++s) {
            const int ai0 = (s * 64 + rA) * 4 + tig;
            const int ai1 = (s * 64 + rB) * 4 + tig;
            const uint2 ah0 = __ldcg(rhHi + ai0);
            const uint2 ah1 = __ldcg(rhHi + ai1);
            const uint2 al0 = __ldcg(rhLo + ai0);
            const uint2 al1 = __ldcg(rhLo + ai1);
            const unsigned aH[4] = {ah0.x, ah1.x, ah0.y, ah1.y};
            const unsigned aL[4] = {al0.x, al1.x, al0.y, al1.y};
            const int bi = s * 32 + tig * 8 + gid;
            mma3(cn, aH, aL, ws2[4 * 4096 + bi], ws2[5 * 4096 + bi]);
        }
        if (kh == 1) {
            float* rb = red + (mt * 32 + lane) * 8;
#pragma unroll
            for (int i = 0; i < 4; ++i) rb[i] = cn[i];
        }
        __syncthreads();
        if (kh == 0) {
            const float* rb = red + (mt * 32 + lane) * 8;
#pragma unroll
            for (int i = 0; i < 4; ++i) cn[i] += rb[i];
#pragma unroll
            for (int v = 0; v < 4; ++v) {
                const int row = (v < 2) ? rA : rB;
                const int col = (v & 1) ? ccol1 : ccol0;
                const size_t gidx = ((size_t)t * BATCH + row) * HD + col;
                const float n = tanhf(cn[v] + __ldg(gn + gidx));
                const float hn = (1.0f - zf[v]) * n + zf[v] * hv[v];
                g_h[row * HD + col] = hn;
                unsigned hi, lo; tf32split(hn, hi, lo);
                const int j = col & 7;
                const int word = (((col >> 3) * 64 + row) * 4 + (j & 3)) * 2 + (j >> 2);
                g_hA_hi[word] = hi;
                g_hA_lo[word] = lo;
                __stcs(out + ((size_t)row * SEQ + t) * HD + col, hn);
                if (t == SEQ - 1)
                    __stcs(out + OUT_OFF + (size_t)row * HD + col, hn);
            }
        }
        group_sync(cnt, gen);
    }
}

// ---------------- launch ----------------
extern "C" void kernel_launch(void* const* d_in, const int* in_sizes, int n_in,
                              void* d_out, int out_size)
{
    const float* x  = (const float*)d_in[0];
    const float* Wi = (const float*)d_in[1];
    const float* bi = (const float*)d_in[2];
    const float* Wz = (const float*)d_in[3];
    const float* bz = (const float*)d_in[4];
    const float* Wr = (const float*)d_in[5];
    const float* br = (const float*)d_in[6];
    const float* Wn = (const float*)d_in[7];
    const float* bn = (const float*)d_in[8];
    float* out = (float*)d_out;

    float* xp;   cudaGetSymbolAddress((void**)&xp,   g_xp);
    float* gate; cudaGetSymbolAddress((void**)&gate, g_gate);

    const dim3 gg(HD / 128, MTOT / 128);   // (8, 256)

    init_h<<<192, 256>>>();
    prep_w<<<12288, 256>>>(Wz, Wr, Wn);

    cudaFuncSetAttribute(sgemm_tf32, cudaFuncAttributeMaxDynamicSharedMemorySize, SMEM_GEMM);
    sgemm_tf32<<<gg, 256, SMEM_GEMM>>>(x, Wi, bi, xp, MTOT, HD, IDIM, 0);
    sgemm_tf32<<<gg, 256, SMEM_GEMM>>>(xp, Wz, bz, gate,                                MTOT, HD, HD, 1);
    sgemm_tf32<<<gg, 256, SMEM_GEMM>>>(xp, Wr, br, gate + (size_t)SEQ * BATCH * HD,     MTOT, HD, HD, 1);
    sgemm_tf32<<<gg, 256, SMEM_GEMM>>>(xp, Wn, bn, gate + (size_t)2 * SEQ * BATCH * HD, MTOT, HD, HD, 1);

    cudaFuncSetAttribute(gru_rec_tc, cudaFuncAttributeMaxDynamicSharedMemorySize, SMEM_REC);
    gru_rec_tc<<<RCTAS, 256, SMEM_REC>>>(out, 0, SEQ / 2);
    gru_rec_tc<<<RCTAS, 256, SMEM_REC>>>(out, SEQ / 2, SEQ);
}